// round 8
// baseline (speedup 1.0000x reference)
#include <cuda_runtime.h>
#include <cuda_bf16.h>
#include <math.h>
#include <stdint.h>

#define N_NODES 50000
#define N_EDGES 800000
#define NHEADS 4
#define NEG_SLOPE 0.2f

// ---------------- static device scratch (no allocs allowed) ----------------
__device__ __align__(16) float g_feat[N_NODES * 256];   // per-layer linear output [N, H*D]
__device__ __align__(16) float g_x1[N_NODES * 128];     // layer-1 output (fp32, residual use)
__device__ __align__(16) float g_x2[N_NODES * 128];     // layer-2 output
__device__ __align__(16) float g_res3[N_NODES * 256];   // layer-3 residual projection
__device__ __align__(16) float g_agg3[N_NODES * 256];   // layer-3 aggregated output
__device__ float g_el[N_NODES * NHEADS];
__device__ float g_er[N_NODES * NHEADS];
__device__ int   g_cnt[N_NODES];
__device__ int   g_off[N_NODES + 1];
__device__ int   g_cur[N_NODES];
__device__ int   g_csrc[N_EDGES];
// bf16 split operands for the tensor-core GEMM
__device__ __align__(16) __nv_bfloat16 g_xhi[N_NODES * 128];
__device__ __align__(16) __nv_bfloat16 g_xlo[N_NODES * 128];
__device__ __align__(16) __nv_bfloat16 g_wthi[256 * 128];   // W transposed: [m][k]
__device__ __align__(16) __nv_bfloat16 g_wtlo[256 * 128];

// ================= warp-MMA helpers (baseline sm_80 PTX — no arch-feature
// suffix; tcgen05 is rejected because the harness lowers via compute_103) ====
__device__ __forceinline__ uint32_t cvta_smem(const void* p) {
    uint32_t a;
    asm("{ .reg .u64 t; cvta.to.shared.u64 t, %1; cvt.u32.u64 %0, t; }" : "=r"(a) : "l"(p));
    return a;
}
#define LDSM_X4(R0, R1, R2, R3, ADDR) \
    asm volatile("ldmatrix.sync.aligned.m8n8.x4.shared.b16 {%0,%1,%2,%3}, [%4];" \
                 : "=r"(R0), "=r"(R1), "=r"(R2), "=r"(R3) : "r"(ADDR))
#define MMA_BF16(C, A0, A1, A2, A3, B0, B1) \
    asm volatile("mma.sync.aligned.m16n8k16.row.col.f32.bf16.bf16.f32 " \
                 "{%0,%1,%2,%3},{%4,%5,%6,%7},{%8,%9},{%0,%1,%2,%3};" \
                 : "+f"((C)[0]), "+f"((C)[1]), "+f"((C)[2]), "+f"((C)[3]) \
                 : "r"(A0), "r"(A1), "r"(A2), "r"(A3), "r"(B0), "r"(B1))

// ---------------- CSR build ----------------
__global__ void zero_cnt_kernel() {
    int i = blockIdx.x * blockDim.x + threadIdx.x;
    if (i < N_NODES) g_cnt[i] = 0;
}

__global__ void hist_kernel(const int* __restrict__ dst) {
    int e = blockIdx.x * blockDim.x + threadIdx.x;
    if (e < N_EDGES) atomicAdd(&g_cnt[dst[e]], 1);
}

__global__ void scan_kernel() {
    __shared__ int wsum[32];
    __shared__ int carry_s;
    int tid = threadIdx.x, lane = tid & 31, wid = tid >> 5;
    if (tid == 0) carry_s = 0;
    __syncthreads();
    for (int base = 0; base < N_NODES; base += 1024) {
        int v = (base + tid < N_NODES) ? g_cnt[base + tid] : 0;
        int x = v;
        #pragma unroll
        for (int o = 1; o < 32; o <<= 1) {
            int t = __shfl_up_sync(0xffffffffu, x, o);
            if (lane >= o) x += t;
        }
        if (lane == 31) wsum[wid] = x;
        __syncthreads();
        if (wid == 0) {
            int y = wsum[lane];
            #pragma unroll
            for (int o = 1; o < 32; o <<= 1) {
                int t = __shfl_up_sync(0xffffffffu, y, o);
                if (lane >= o) y += t;
            }
            wsum[lane] = y;
        }
        __syncthreads();
        int excl = carry_s + x - v + (wid ? wsum[wid - 1] : 0);
        if (base + tid < N_NODES) {
            g_off[base + tid] = excl;
            g_cur[base + tid] = excl;
        }
        __syncthreads();
        if (tid == 0) carry_s += wsum[31];
        __syncthreads();
    }
    if (tid == 0) g_off[N_NODES] = carry_s;
}

__global__ void scatter_kernel(const int* __restrict__ src, const int* __restrict__ dst) {
    int e = blockIdx.x * blockDim.x + threadIdx.x;
    if (e < N_EDGES) {
        int d = dst[e];
        int p = atomicAdd(&g_cur[d], 1);
        g_csrc[p] = src[e];
    }
}

// ---------------- precision-split converts ----------------
__global__ void convert_x_kernel(const float* __restrict__ x) {
    int i = blockIdx.x * blockDim.x + threadIdx.x;
    if (i < N_NODES * 128) {
        float v = x[i];
        __nv_bfloat16 hi = __float2bfloat16(v);
        g_xhi[i] = hi;
        g_xlo[i] = __float2bfloat16(v - __bfloat162float(hi));
    }
}

// W[128,M] fp32 -> Wt[m][k] bf16 hi/lo
__global__ void convert_w_kernel(const float* __restrict__ W, int M) {
    int i = blockIdx.x * blockDim.x + threadIdx.x;
    if (i < M * 128) {
        int m = i >> 7, k = i & 127;
        float v = W[k * M + m];
        __nv_bfloat16 hi = __float2bfloat16(v);
        g_wthi[i] = hi;
        g_wtlo[i] = __float2bfloat16(v - __bfloat162float(hi));
    }
}

// ---------------- tensor-core GEMM (split-bf16, mma.sync) + el/er epilogue ---
// out[128x128 tile] = Xsplit @ Wtsplit^T with 3 split MMAs (hi*hi+hi*lo+lo*hi).
// A, B tiles both stored row-major [idx][k] with pitch 136 bf16 (272B): row
// stride mod 128B = 16 -> LDSM phase-conflict-free.
// Warp w owns rows [w*16, w*16+16). Fragments per m16n8k16:
//   A: a0=(g,2t|k0-7) a1=(g+8,2t) a2=(g,2t+8) a3=(g+8,2t+8)   g=lane>>2,t=lane&3
//   B: b0=(2t,n=g|k0-7) b1=(2t+8,n=g)  <- ldmatrix (non-trans) on [n][k] rows
//   C: c0=C[g][2t] c1=C[g][2t+1] c2=C[g+8][2t] c3=C[g+8][2t+1]
// Epilogue: el/er = dot(feat_row, al/ar) -- thread-local over owned col pairs,
// reduced across the quad (shfl_xor 1,2), bucketed per head.
#define APITCH 136
#define MMA_SMEM_BYTES (4 * 128 * APITCH * 2)

__global__ void __launch_bounds__(256, 1) mma_gemm_kernel(float* __restrict__ out, int M,
        const float* __restrict__ al, const float* __restrict__ ar, int DA) {
    extern __shared__ __nv_bfloat16 sm[];
    __nv_bfloat16* Ahi = sm;
    __nv_bfloat16* Alo = Ahi + 128 * APITCH;
    __nv_bfloat16* Bhi = Alo + 128 * APITCH;
    __nv_bfloat16* Blo = Bhi + 128 * APITCH;
    int tid = threadIdx.x, lane = tid & 31, w = tid >> 5;
    int row0 = blockIdx.x * 128, col0 = blockIdx.y * 128;

    // cooperative tile load (A rows may run past N_NODES -> zero-fill)
    for (int i = tid; i < 2048; i += 256) {
        int r = i >> 4, c = (i & 15) * 8;
        int gr = row0 + r;
        uint4 vh = make_uint4(0, 0, 0, 0), vl = vh;
        if (gr < N_NODES) {
            vh = *(const uint4*)(g_xhi + gr * 128 + c);
            vl = *(const uint4*)(g_xlo + gr * 128 + c);
        }
        *(uint4*)(Ahi + r * APITCH + c) = vh;
        *(uint4*)(Alo + r * APITCH + c) = vl;
        int gn = col0 + r;   // weight output-column index (< M <= 256)
        *(uint4*)(Bhi + r * APITCH + c) = *(const uint4*)(g_wthi + gn * 128 + c);
        *(uint4*)(Blo + r * APITCH + c) = *(const uint4*)(g_wtlo + gn * 128 + c);
    }
    __syncthreads();

    float c[16][4];
    #pragma unroll
    for (int i = 0; i < 16; i++)
        #pragma unroll
        for (int j = 0; j < 4; j++) c[i][j] = 0.f;

    // ldmatrix lane-address precompute
    int l7 = lane & 7, mi = lane >> 3;
    int arow = w * 16 + (mi & 1) * 8 + l7;       // m0:r0-7/k0 m1:r8-15/k0 m2:r0-7/k8 m3:r8-15/k8
    int akof = (mi >> 1) * 8;
    uint32_t a_hi_ad = cvta_smem(Ahi) + (uint32_t)(arow * APITCH + akof) * 2;
    uint32_t a_lo_ad = cvta_smem(Alo) + (uint32_t)(arow * APITCH + akof) * 2;
    int bn = (mi >> 1) * 8 + l7;                 // m0:n0-7/k0 m1:n0-7/k8 m2:n8-15/k0 m3:n8-15/k8
    int bkof = (mi & 1) * 8;
    uint32_t b_hi_ad = cvta_smem(Bhi) + (uint32_t)(bn * APITCH + bkof) * 2;
    uint32_t b_lo_ad = cvta_smem(Blo) + (uint32_t)(bn * APITCH + bkof) * 2;

    for (int ks = 0; ks < 8; ks++) {
        uint32_t ah0, ah1, ah2, ah3, al0r, al1r, al2r, al3r;
        LDSM_X4(ah0, ah1, ah2, ah3, a_hi_ad + ks * 32);   // 16 bf16 = 32B per k-step
        LDSM_X4(al0r, al1r, al2r, al3r, a_lo_ad + ks * 32);
        #pragma unroll
        for (int np = 0; np < 8; np++) {
            uint32_t bh0, bh1, bh2, bh3, bl0, bl1, bl2, bl3;
            uint32_t bo = (uint32_t)(np * 16 * APITCH) * 2 + ks * 32;
            LDSM_X4(bh0, bh1, bh2, bh3, b_hi_ad + bo);
            LDSM_X4(bl0, bl1, bl2, bl3, b_lo_ad + bo);
            int nt = 2 * np;
            MMA_BF16(c[nt],     ah0, ah1, ah2, ah3, bh0, bh1);
            MMA_BF16(c[nt],     ah0, ah1, ah2, ah3, bl0, bl1);
            MMA_BF16(c[nt],     al0r, al1r, al2r, al3r, bh0, bh1);
            MMA_BF16(c[nt + 1], ah0, ah1, ah2, ah3, bh2, bh3);
            MMA_BF16(c[nt + 1], ah0, ah1, ah2, ah3, bl2, bl3);
            MMA_BF16(c[nt + 1], al0r, al1r, al2r, al3r, bh2, bh3);
        }
    }

    // epilogue: store feat + fused el/er
    int t = lane & 3, g2 = lane >> 2;
    int rlo = row0 + w * 16 + g2, rhi = rlo + 8;
    float elL[4] = {0, 0, 0, 0}, erL[4] = {0, 0, 0, 0};
    float elH[4] = {0, 0, 0, 0}, erH[4] = {0, 0, 0, 0};
    #pragma unroll
    for (int nt = 0; nt < 16; nt++) {
        int gc = col0 + nt * 8 + 2 * t;
        if (rlo < N_NODES)
            *(float2*)(out + rlo * M + gc) = make_float2(c[nt][0], c[nt][1]);
        if (rhi < N_NODES)
            *(float2*)(out + rhi * M + gc) = make_float2(c[nt][2], c[nt][3]);
        if (DA) {
            int b = (DA == 32) ? (nt >> 2) : (nt >> 3);
            float a0v = al[gc], a1v = al[gc + 1];
            float r0v = ar[gc], r1v = ar[gc + 1];
            elL[b] += c[nt][0] * a0v + c[nt][1] * a1v;
            erL[b] += c[nt][0] * r0v + c[nt][1] * r1v;
            elH[b] += c[nt][2] * a0v + c[nt][3] * a1v;
            erH[b] += c[nt][2] * r0v + c[nt][3] * r1v;
        }
    }
    if (DA) {
        int nb = 128 / DA;   // 4 (DA=32) or 2 (DA=64)
        #pragma unroll
        for (int b = 0; b < 4; b++) {
            if (b >= nb) break;
            #pragma unroll
            for (int o = 1; o < 4; o <<= 1) {   // reduce across the quad (t lanes)
                elL[b] += __shfl_xor_sync(0xffffffffu, elL[b], o);
                erL[b] += __shfl_xor_sync(0xffffffffu, erL[b], o);
                elH[b] += __shfl_xor_sync(0xffffffffu, elH[b], o);
                erH[b] += __shfl_xor_sync(0xffffffffu, erH[b], o);
            }
            if (t == 0) {
                int h = col0 / DA + b;
                if (rlo < N_NODES) {
                    g_el[rlo * NHEADS + h] = elL[b];
                    g_er[rlo * NHEADS + h] = erL[b];
                }
                if (rhi < N_NODES) {
                    g_el[rhi * NHEADS + h] = elH[b];
                    g_er[rhi * NHEADS + h] = erH[b];
                }
            }
        }
    }
}

// ---------------- fused edge softmax + aggregation ----------------
// one warp per (node, head); pass 1 segment-max, pass 2 exp + gather. No atomics.
__global__ void attn_aggr_kernel(const float* __restrict__ res, float* __restrict__ out,
                                 int D, int M, int relu, int wbf) {
    int gw = (blockIdx.x * blockDim.x + threadIdx.x) >> 5;
    if (gw >= N_NODES * NHEADS) return;
    int n = gw >> 2, h = gw & 3;
    int lane = threadIdx.x & 31;
    int beg = g_off[n], end = g_off[n + 1];

    float erv = g_er[n * NHEADS + h];

    float m = -1e30f;
    for (int j = beg + lane; j < end; j += 32) {
        int s = g_csrc[j];
        float e = g_el[s * NHEADS + h] + erv;
        e = e > 0.f ? e : NEG_SLOPE * e;
        m = fmaxf(m, e);
    }
    #pragma unroll
    for (int o = 16; o; o >>= 1) m = fmaxf(m, __shfl_xor_sync(0xffffffffu, m, o));

    float den = 0.f, acc0 = 0.f, acc1 = 0.f;
    for (int j0 = beg; j0 < end; j0 += 32) {
        int j = j0 + lane;
        float w = 0.f;
        int s = 0;
        if (j < end) {
            s = g_csrc[j];
            float e = g_el[s * NHEADS + h] + erv;
            e = e > 0.f ? e : NEG_SLOPE * e;
            w = __expf(e - m);
        }
        den += w;
        int cnt = min(32, end - j0);
        for (int t = 0; t < cnt; t++) {
            float wt = __shfl_sync(0xffffffffu, w, t);
            int st = __shfl_sync(0xffffffffu, s, t);
            const float* fp = g_feat + st * M + h * D;
            acc0 = fmaf(wt, fp[lane], acc0);
            if (D == 64) acc1 = fmaf(wt, fp[lane + 32], acc1);
        }
    }
    #pragma unroll
    for (int o = 16; o; o >>= 1) den += __shfl_xor_sync(0xffffffffu, den, o);
    float inv = (end > beg) ? (1.f / den) : 0.f;

    int base = n * M + h * D;
    float v0 = fmaf(acc0, inv, res[base + lane]);
    if (relu) v0 = fmaxf(v0, 0.f);
    out[base + lane] = v0;
    if (wbf) {  // produce next layer's bf16 split input (M==128 layers only)
        __nv_bfloat16 hi = __float2bfloat16(v0);
        g_xhi[base + lane] = hi;
        g_xlo[base + lane] = __float2bfloat16(v0 - __bfloat162float(hi));
    }
    if (D == 64) {
        float v1 = fmaf(acc1, inv, res[base + lane + 32]);
        if (relu) v1 = fmaxf(v1, 0.f);
        out[base + lane + 32] = v1;
    }
}

// ---------------- final mean over heads ----------------
__global__ void mean_kernel(float* __restrict__ out) {
    int idx = blockIdx.x * blockDim.x + threadIdx.x;
    if (idx >= N_NODES * 64) return;
    int n = idx >> 6, d = idx & 63;
    const float* p = g_agg3 + n * 256 + d;
    out[idx] = 0.25f * (p[0] + p[64] + p[128] + p[192]);
}

// ---------------- launch ----------------
// NOTE: device buffers passed as kernel args from host MUST come from
// cudaGetSymbolAddress (host symbol decay = host shadow address; on GB300 ATS
// the GPU silently writes host RAM). Device-side references to globals are fine.
#define GRID_ROWS ((N_NODES + 127) / 128)

extern "C" void kernel_launch(void* const* d_in, const int* in_sizes, int n_in,
                              void* d_out, int out_size) {
    const float* h     = (const float*)d_in[0];
    const float* W1    = (const float*)d_in[1];
    const float* al1   = (const float*)d_in[2];
    const float* ar1   = (const float*)d_in[3];
    const float* W2    = (const float*)d_in[4];
    const float* al2   = (const float*)d_in[5];
    const float* ar2   = (const float*)d_in[6];
    const float* W3    = (const float*)d_in[7];
    const float* al3   = (const float*)d_in[8];
    const float* ar3   = (const float*)d_in[9];
    const float* resW3 = (const float*)d_in[10];
    const int*   src   = (const int*)d_in[11];
    const int*   dst   = (const int*)d_in[12];
    float* out = (float*)d_out;

    float* g_feat_p; cudaGetSymbolAddress((void**)&g_feat_p, g_feat);
    float* g_x1_p;   cudaGetSymbolAddress((void**)&g_x1_p, g_x1);
    float* g_x2_p;   cudaGetSymbolAddress((void**)&g_x2_p, g_x2);
    float* g_res3_p; cudaGetSymbolAddress((void**)&g_res3_p, g_res3);
    float* g_agg3_p; cudaGetSymbolAddress((void**)&g_agg3_p, g_agg3);

    cudaFuncSetAttribute(mma_gemm_kernel, cudaFuncAttributeMaxDynamicSharedMemorySize,
                         MMA_SMEM_BYTES);

    // CSR build (dst-indexed), reused by all 3 layers
    zero_cnt_kernel<<<(N_NODES + 255) / 256, 256>>>();
    hist_kernel<<<(N_EDGES + 255) / 256, 256>>>(dst);
    scan_kernel<<<1, 1024>>>();
    scatter_kernel<<<(N_EDGES + 255) / 256, 256>>>(src, dst);

    // bf16 split of layer-1 input
    convert_x_kernel<<<(N_NODES * 128 + 255) / 256, 256>>>(h);

    // ---- Layer 1: 128 -> 4x32, residual = h, relu; aggr also emits bf16 x1
    convert_w_kernel<<<(128 * 128 + 255) / 256, 256>>>(W1, 128);
    mma_gemm_kernel<<<dim3(GRID_ROWS, 1), 256, MMA_SMEM_BYTES>>>(g_feat_p, 128, al1, ar1, 32);
    attn_aggr_kernel<<<(N_NODES * NHEADS * 32 + 255) / 256, 256>>>(h, g_x1_p, 32, 128, 1, 1);

    // ---- Layer 2: 128 -> 4x32, residual = x1, relu; aggr emits bf16 x2
    convert_w_kernel<<<(128 * 128 + 255) / 256, 256>>>(W2, 128);
    mma_gemm_kernel<<<dim3(GRID_ROWS, 1), 256, MMA_SMEM_BYTES>>>(g_feat_p, 128, al2, ar2, 32);
    attn_aggr_kernel<<<(N_NODES * NHEADS * 32 + 255) / 256, 256>>>(g_x1_p, g_x2_p, 32, 128, 1, 1);

    // ---- Layer 3 residual projection: res3 = x2 @ resW3  (no attention epilogue)
    convert_w_kernel<<<(256 * 128 + 255) / 256, 256>>>(resW3, 256);
    mma_gemm_kernel<<<dim3(GRID_ROWS, 2), 256, MMA_SMEM_BYTES>>>(g_res3_p, 256, nullptr, nullptr, 0);

    // ---- Layer 3: 128 -> 4x64, residual = res3, no act
    convert_w_kernel<<<(256 * 128 + 255) / 256, 256>>>(W3, 256);
    mma_gemm_kernel<<<dim3(GRID_ROWS, 2), 256, MMA_SMEM_BYTES>>>(g_feat_p, 256, al3, ar3, 64);
    attn_aggr_kernel<<<(N_NODES * NHEADS * 32 + 255) / 256, 256>>>(g_res3_p, g_agg3_p, 64, 256, 0, 0);

    // mean over heads -> [N, 64]
    mean_kernel<<<(N_NODES * 64 + 255) / 256, 256>>>(out);
}

// round 12
// speedup vs baseline: 1.7029x; 1.7029x over previous
#include <cuda_runtime.h>
#include <cuda_bf16.h>
#include <math.h>
#include <stdint.h>

#define N_NODES 50000
#define N_EDGES 800000
#define NHEADS 4
#define NEG_SLOPE 0.2f

// ---------------- static device scratch (no allocs allowed) ----------------
__device__ __align__(16) float g_feat[N_NODES * 256];   // per-layer linear output [N, H*D]
__device__ __align__(16) float g_x1[N_NODES * 128];     // layer-1 output (fp32, residual use)
__device__ __align__(16) float g_x2[N_NODES * 128];     // layer-2 output
__device__ __align__(16) float g_res3[N_NODES * 256];   // layer-3 residual projection
__device__ __align__(16) float g_el[N_NODES * NHEADS];
__device__ __align__(16) float g_er[N_NODES * NHEADS];
__device__ int   g_cnt[N_NODES];
__device__ int   g_off[N_NODES + 1];
__device__ int   g_cur[N_NODES];
__device__ int   g_csrc[N_EDGES];
// bf16 split operands for the tensor-core GEMM
__device__ __align__(16) __nv_bfloat16 g_xhi[N_NODES * 128];
__device__ __align__(16) __nv_bfloat16 g_xlo[N_NODES * 128];
// all weight splits, transposed [m][k]: W1 @0, W2 @16384, W3 @32768, resW3 @65536
__device__ __align__(16) __nv_bfloat16 g_wthi[98304];
__device__ __align__(16) __nv_bfloat16 g_wtlo[98304];

// ================= warp-MMA helpers (baseline sm_80 PTX — no arch-feature
// suffix; tcgen05 is rejected because the harness lowers via compute_103) ====
__device__ __forceinline__ uint32_t cvta_smem(const void* p) {
    uint32_t a;
    asm("{ .reg .u64 t; cvta.to.shared.u64 t, %1; cvt.u32.u64 %0, t; }" : "=r"(a) : "l"(p));
    return a;
}
#define LDSM_X4(R0, R1, R2, R3, ADDR) \
    asm volatile("ldmatrix.sync.aligned.m8n8.x4.shared.b16 {%0,%1,%2,%3}, [%4];" \
                 : "=r"(R0), "=r"(R1), "=r"(R2), "=r"(R3) : "r"(ADDR))
#define MMA_BF16(C, A0, A1, A2, A3, B0, B1) \
    asm volatile("mma.sync.aligned.m16n8k16.row.col.f32.bf16.bf16.f32 " \
                 "{%0,%1,%2,%3},{%4,%5,%6,%7},{%8,%9},{%0,%1,%2,%3};" \
                 : "+f"((C)[0]), "+f"((C)[1]), "+f"((C)[2]), "+f"((C)[3]) \
                 : "r"(A0), "r"(A1), "r"(A2), "r"(A3), "r"(B0), "r"(B1))

// ---------------- CSR build ----------------
__global__ void hist_kernel(const int* __restrict__ dst) {
    int e = blockIdx.x * blockDim.x + threadIdx.x;
    if (e < N_EDGES) atomicAdd(&g_cnt[dst[e]], 1);
}

__global__ void scan_kernel() {
    __shared__ int wsum[32];
    __shared__ int carry_s;
    int tid = threadIdx.x, lane = tid & 31, wid = tid >> 5;
    if (tid == 0) carry_s = 0;
    __syncthreads();
    for (int base = 0; base < N_NODES; base += 1024) {
        int v = (base + tid < N_NODES) ? g_cnt[base + tid] : 0;
        int x = v;
        #pragma unroll
        for (int o = 1; o < 32; o <<= 1) {
            int t = __shfl_up_sync(0xffffffffu, x, o);
            if (lane >= o) x += t;
        }
        if (lane == 31) wsum[wid] = x;
        __syncthreads();
        if (wid == 0) {
            int y = wsum[lane];
            #pragma unroll
            for (int o = 1; o < 32; o <<= 1) {
                int t = __shfl_up_sync(0xffffffffu, y, o);
                if (lane >= o) y += t;
            }
            wsum[lane] = y;
        }
        __syncthreads();
        int excl = carry_s + x - v + (wid ? wsum[wid - 1] : 0);
        if (base + tid < N_NODES) {
            g_off[base + tid] = excl;
            g_cur[base + tid] = excl;
        }
        __syncthreads();
        if (tid == 0) carry_s += wsum[31];
        __syncthreads();
    }
    if (tid == 0) g_off[N_NODES] = carry_s;
}

__global__ void scatter_kernel(const int* __restrict__ src, const int* __restrict__ dst) {
    int e = blockIdx.x * blockDim.x + threadIdx.x;
    if (e < N_EDGES) {
        int d = dst[e];
        int p = atomicAdd(&g_cur[d], 1);
        g_csrc[p] = src[e];
    }
}

// ---------------- precision-split converts (also zeroes g_cnt) --------------
__global__ void convert_x_kernel(const float* __restrict__ x) {
    int i = blockIdx.x * blockDim.x + threadIdx.x;
    if (i < N_NODES) g_cnt[i] = 0;
    if (i < N_NODES * 128) {
        float v = x[i];
        __nv_bfloat16 hi = __float2bfloat16(v);
        g_xhi[i] = hi;
        g_xlo[i] = __float2bfloat16(v - __bfloat162float(hi));
    }
}

// all four weight matrices -> transposed bf16 hi/lo in one launch
__global__ void convert_w_all_kernel(const float* __restrict__ W1, const float* __restrict__ W2,
                                     const float* __restrict__ W3, const float* __restrict__ rW3) {
    int i = blockIdx.x * blockDim.x + threadIdx.x;
    if (i >= 98304) return;
    const float* W;
    int M, off;
    if (i < 16384)      { W = W1;  M = 128; off = i; }
    else if (i < 32768) { W = W2;  M = 128; off = i - 16384; }
    else if (i < 65536) { W = W3;  M = 256; off = i - 32768; }
    else                { W = rW3; M = 256; off = i - 65536; }
    int m = off >> 7, k = off & 127;
    float v = W[k * M + m];
    __nv_bfloat16 hi = __float2bfloat16(v);
    g_wthi[i] = hi;
    g_wtlo[i] = __float2bfloat16(v - __bfloat162float(hi));
}

// ---------------- tensor-core GEMM (split-bf16, mma.sync) + el/er epilogue ---
#define APITCH 136
#define MMA_SMEM_BYTES (4 * 128 * APITCH * 2)

__global__ void __launch_bounds__(256, 1) mma_gemm_kernel(float* __restrict__ out, int M,
        const __nv_bfloat16* __restrict__ whi, const __nv_bfloat16* __restrict__ wlo,
        const float* __restrict__ al, const float* __restrict__ ar, int DA) {
    extern __shared__ __nv_bfloat16 sm[];
    __nv_bfloat16* Ahi = sm;
    __nv_bfloat16* Alo = Ahi + 128 * APITCH;
    __nv_bfloat16* Bhi = Alo + 128 * APITCH;
    __nv_bfloat16* Blo = Bhi + 128 * APITCH;
    int tid = threadIdx.x, lane = tid & 31, w = tid >> 5;
    int row0 = blockIdx.x * 128, col0 = blockIdx.y * 128;

    for (int i = tid; i < 2048; i += 256) {
        int r = i >> 4, c = (i & 15) * 8;
        int gr = row0 + r;
        uint4 vh = make_uint4(0, 0, 0, 0), vl = vh;
        if (gr < N_NODES) {
            vh = *(const uint4*)(g_xhi + gr * 128 + c);
            vl = *(const uint4*)(g_xlo + gr * 128 + c);
        }
        *(uint4*)(Ahi + r * APITCH + c) = vh;
        *(uint4*)(Alo + r * APITCH + c) = vl;
        int gn = col0 + r;
        *(uint4*)(Bhi + r * APITCH + c) = *(const uint4*)(whi + gn * 128 + c);
        *(uint4*)(Blo + r * APITCH + c) = *(const uint4*)(wlo + gn * 128 + c);
    }
    __syncthreads();

    float c[16][4];
    #pragma unroll
    for (int i = 0; i < 16; i++)
        #pragma unroll
        for (int j = 0; j < 4; j++) c[i][j] = 0.f;

    int l7 = lane & 7, mi = lane >> 3;
    int arow = w * 16 + (mi & 1) * 8 + l7;
    int akof = (mi >> 1) * 8;
    uint32_t a_hi_ad = cvta_smem(Ahi) + (uint32_t)(arow * APITCH + akof) * 2;
    uint32_t a_lo_ad = cvta_smem(Alo) + (uint32_t)(arow * APITCH + akof) * 2;
    int bn = (mi >> 1) * 8 + l7;
    int bkof = (mi & 1) * 8;
    uint32_t b_hi_ad = cvta_smem(Bhi) + (uint32_t)(bn * APITCH + bkof) * 2;
    uint32_t b_lo_ad = cvta_smem(Blo) + (uint32_t)(bn * APITCH + bkof) * 2;

    for (int ks = 0; ks < 8; ks++) {
        uint32_t ah0, ah1, ah2, ah3, al0r, al1r, al2r, al3r;
        LDSM_X4(ah0, ah1, ah2, ah3, a_hi_ad + ks * 32);
        LDSM_X4(al0r, al1r, al2r, al3r, a_lo_ad + ks * 32);
        #pragma unroll
        for (int np = 0; np < 8; np++) {
            uint32_t bh0, bh1, bh2, bh3, bl0, bl1, bl2, bl3;
            uint32_t bo = (uint32_t)(np * 16 * APITCH) * 2 + ks * 32;
            LDSM_X4(bh0, bh1, bh2, bh3, b_hi_ad + bo);
            LDSM_X4(bl0, bl1, bl2, bl3, b_lo_ad + bo);
            int nt = 2 * np;
            MMA_BF16(c[nt],     ah0, ah1, ah2, ah3, bh0, bh1);
            MMA_BF16(c[nt],     ah0, ah1, ah2, ah3, bl0, bl1);
            MMA_BF16(c[nt],     al0r, al1r, al2r, al3r, bh0, bh1);
            MMA_BF16(c[nt + 1], ah0, ah1, ah2, ah3, bh2, bh3);
            MMA_BF16(c[nt + 1], ah0, ah1, ah2, ah3, bl2, bl3);
            MMA_BF16(c[nt + 1], al0r, al1r, al2r, al3r, bh2, bh3);
        }
    }

    int t = lane & 3, g2 = lane >> 2;
    int rlo = row0 + w * 16 + g2, rhi = rlo + 8;
    float elL[4] = {0, 0, 0, 0}, erL[4] = {0, 0, 0, 0};
    float elH[4] = {0, 0, 0, 0}, erH[4] = {0, 0, 0, 0};
    #pragma unroll
    for (int nt = 0; nt < 16; nt++) {
        int gc = col0 + nt * 8 + 2 * t;
        if (rlo < N_NODES)
            *(float2*)(out + rlo * M + gc) = make_float2(c[nt][0], c[nt][1]);
        if (rhi < N_NODES)
            *(float2*)(out + rhi * M + gc) = make_float2(c[nt][2], c[nt][3]);
        if (DA) {
            int b = (DA == 32) ? (nt >> 2) : (nt >> 3);
            float a0v = al[gc], a1v = al[gc + 1];
            float r0v = ar[gc], r1v = ar[gc + 1];
            elL[b] += c[nt][0] * a0v + c[nt][1] * a1v;
            erL[b] += c[nt][0] * r0v + c[nt][1] * r1v;
            elH[b] += c[nt][2] * a0v + c[nt][3] * a1v;
            erH[b] += c[nt][2] * r0v + c[nt][3] * r1v;
        }
    }
    if (DA) {
        int nb = 128 / DA;
        #pragma unroll
        for (int b = 0; b < 4; b++) {
            if (b >= nb) break;
            #pragma unroll
            for (int o = 1; o < 4; o <<= 1) {
                elL[b] += __shfl_xor_sync(0xffffffffu, elL[b], o);
                erL[b] += __shfl_xor_sync(0xffffffffu, erL[b], o);
                elH[b] += __shfl_xor_sync(0xffffffffu, elH[b], o);
                erH[b] += __shfl_xor_sync(0xffffffffu, erH[b], o);
            }
            if (t == 0) {
                int h = col0 / DA + b;
                if (rlo < N_NODES) {
                    g_el[rlo * NHEADS + h] = elL[b];
                    g_er[rlo * NHEADS + h] = erL[b];
                }
                if (rhi < N_NODES) {
                    g_el[rhi * NHEADS + h] = elH[b];
                    g_er[rhi * NHEADS + h] = erH[b];
                }
            }
        }
    }
}

// ---------------- fused edge softmax + aggregation: warp per NODE ----------
// All 4 heads processed by one warp. No max-pass: e = leakyrelu(el+er) has
// |e| ~ 2 here, exp(e) cannot overflow (clamped at 60); softmax without the
// max shift is mathematically identical, fp delta ~1e-7.
// Per 32-edge chunk: each lane computes its edge's (s, w4) -> smem stage ->
// gather loop with independent iterations (LDS s, LDS w, LDG.128 feat, FMA),
// unrolled x4 for MLP.
// FINAL (layer 3, M=256): epilogue adds residual and reduces mean-over-heads
// via shfl_xor(16), writing [N,64] output directly.
// Otherwise (M=128): relu + write fp32 out + emit next layer's bf16 hi/lo.
template<int MM, bool FINAL>
__global__ void __launch_bounds__(256) attn_kernel(const float* __restrict__ res,
                                                   float* __restrict__ out) {
    __shared__ int   sh_s[8][32];
    __shared__ float sh_w[8][128];
    int wslot = threadIdx.x >> 5, lane = threadIdx.x & 31;
    int n = blockIdx.x * 8 + wslot;
    if (n >= N_NODES) return;   // uniform per warp
    int beg = g_off[n], end = g_off[n + 1];
    float4 er4 = *(const float4*)(g_er + n * 4);
    float4 den = make_float4(0.f, 0.f, 0.f, 0.f);
    float4 acc0 = make_float4(0.f, 0.f, 0.f, 0.f);
    float4 acc1 = make_float4(0.f, 0.f, 0.f, 0.f);
    int myh = (MM == 128) ? (lane >> 3) : (lane >> 4);

    for (int j0 = beg; j0 < end; j0 += 32) {
        int j = j0 + lane;
        float4 w4 = make_float4(0.f, 0.f, 0.f, 0.f);
        int s = 0;
        if (j < end) {
            s = g_csrc[j];
            float4 el4 = *(const float4*)(g_el + s * 4);
            float e0 = el4.x + er4.x; e0 = e0 > 0.f ? e0 : NEG_SLOPE * e0;
            float e1 = el4.y + er4.y; e1 = e1 > 0.f ? e1 : NEG_SLOPE * e1;
            float e2 = el4.z + er4.z; e2 = e2 > 0.f ? e2 : NEG_SLOPE * e2;
            float e3 = el4.w + er4.w; e3 = e3 > 0.f ? e3 : NEG_SLOPE * e3;
            w4.x = __expf(fminf(e0, 60.f));
            w4.y = __expf(fminf(e1, 60.f));
            w4.z = __expf(fminf(e2, 60.f));
            w4.w = __expf(fminf(e3, 60.f));
            den.x += w4.x; den.y += w4.y; den.z += w4.z; den.w += w4.w;
        }
        sh_s[wslot][lane] = s;
        *(float4*)&sh_w[wslot][lane * 4] = w4;
        __syncwarp();
        int cnt = min(32, end - j0);
        #pragma unroll 4
        for (int t = 0; t < cnt; t++) {
            int st = sh_s[wslot][t];
            const float* fp = g_feat + st * MM;
            if (MM == 128) {
                float wt = sh_w[wslot][t * 4 + myh];
                float4 f = *(const float4*)(fp + lane * 4);
                acc0.x = fmaf(wt, f.x, acc0.x);
                acc0.y = fmaf(wt, f.y, acc0.y);
                acc0.z = fmaf(wt, f.z, acc0.z);
                acc0.w = fmaf(wt, f.w, acc0.w);
            } else {
                float wt0 = sh_w[wslot][t * 4 + myh];
                float wt1 = sh_w[wslot][t * 4 + 2 + myh];
                float4 f0 = *(const float4*)(fp + lane * 4);
                float4 f1 = *(const float4*)(fp + 128 + lane * 4);
                acc0.x = fmaf(wt0, f0.x, acc0.x);
                acc0.y = fmaf(wt0, f0.y, acc0.y);
                acc0.z = fmaf(wt0, f0.z, acc0.z);
                acc0.w = fmaf(wt0, f0.w, acc0.w);
                acc1.x = fmaf(wt1, f1.x, acc1.x);
                acc1.y = fmaf(wt1, f1.y, acc1.y);
                acc1.z = fmaf(wt1, f1.z, acc1.z);
                acc1.w = fmaf(wt1, f1.w, acc1.w);
            }
        }
        __syncwarp();
    }

    #pragma unroll
    for (int o = 16; o; o >>= 1) {
        den.x += __shfl_xor_sync(0xffffffffu, den.x, o);
        den.y += __shfl_xor_sync(0xffffffffu, den.y, o);
        den.z += __shfl_xor_sync(0xffffffffu, den.z, o);
        den.w += __shfl_xor_sync(0xffffffffu, den.w, o);
    }
    bool ne = end > beg;

    if (MM == 128) {
        float a = (lane & 8) ? den.y : den.x;
        float b = (lane & 8) ? den.w : den.z;
        float dv = (lane & 16) ? b : a;
        float inv = ne ? 1.f / dv : 0.f;
        float4 r = *(const float4*)(res + n * 128 + lane * 4);
        float4 v;
        v.x = fmaxf(fmaf(acc0.x, inv, r.x), 0.f);
        v.y = fmaxf(fmaf(acc0.y, inv, r.y), 0.f);
        v.z = fmaxf(fmaf(acc0.z, inv, r.z), 0.f);
        v.w = fmaxf(fmaf(acc0.w, inv, r.w), 0.f);
        *(float4*)(out + n * 128 + lane * 4) = v;
        // emit next layer's bf16 split input
        __nv_bfloat16 hx = __float2bfloat16(v.x), hy = __float2bfloat16(v.y);
        __nv_bfloat16 hz = __float2bfloat16(v.z), hw = __float2bfloat16(v.w);
        __nv_bfloat162 hA; hA.x = hx; hA.y = hy;
        __nv_bfloat162 hB; hB.x = hz; hB.y = hw;
        *(__nv_bfloat162*)(g_xhi + n * 128 + lane * 4) = hA;
        *(__nv_bfloat162*)(g_xhi + n * 128 + lane * 4 + 2) = hB;
        __nv_bfloat162 lA, lB;
        lA.x = __float2bfloat16(v.x - __bfloat162float(hx));
        lA.y = __float2bfloat16(v.y - __bfloat162float(hy));
        lB.x = __float2bfloat16(v.z - __bfloat162float(hz));
        lB.y = __float2bfloat16(v.w - __bfloat162float(hw));
        *(__nv_bfloat162*)(g_xlo + n * 128 + lane * 4) = lA;
        *(__nv_bfloat162*)(g_xlo + n * 128 + lane * 4 + 2) = lB;
    } else {
        float dv0 = (lane & 16) ? den.y : den.x;
        float dv1 = (lane & 16) ? den.w : den.z;
        float inv0 = ne ? 1.f / dv0 : 0.f;
        float inv1 = ne ? 1.f / dv1 : 0.f;
        float4 r0 = *(const float4*)(res + n * 256 + lane * 4);
        float4 r1 = *(const float4*)(res + n * 256 + 128 + lane * 4);
        float4 v0, v1;
        v0.x = fmaf(acc0.x, inv0, r0.x); v0.y = fmaf(acc0.y, inv0, r0.y);
        v0.z = fmaf(acc0.z, inv0, r0.z); v0.w = fmaf(acc0.w, inv0, r0.w);
        v1.x = fmaf(acc1.x, inv1, r1.x); v1.y = fmaf(acc1.y, inv1, r1.y);
        v1.z = fmaf(acc1.z, inv1, r1.z); v1.w = fmaf(acc1.w, inv1, r1.w);
        // mean over heads: lane l pairs with l^16 (heads 0/1 in v0, 2/3 in v1)
        v0.x += __shfl_xor_sync(0xffffffffu, v0.x, 16);
        v0.y += __shfl_xor_sync(0xffffffffu, v0.y, 16);
        v0.z += __shfl_xor_sync(0xffffffffu, v0.z, 16);
        v0.w += __shfl_xor_sync(0xffffffffu, v0.w, 16);
        v1.x += __shfl_xor_sync(0xffffffffu, v1.x, 16);
        v1.y += __shfl_xor_sync(0xffffffffu, v1.y, 16);
        v1.z += __shfl_xor_sync(0xffffffffu, v1.z, 16);
        v1.w += __shfl_xor_sync(0xffffffffu, v1.w, 16);
        if (lane < 16) {
            float4 tot;
            tot.x = 0.25f * (v0.x + v1.x);
            tot.y = 0.25f * (v0.y + v1.y);
            tot.z = 0.25f * (v0.z + v1.z);
            tot.w = 0.25f * (v0.w + v1.w);
            *(float4*)(out + n * 64 + lane * 4) = tot;
        }
    }
}

// ---------------- launch ----------------
// NOTE: device buffers passed as kernel args from host MUST come from
// cudaGetSymbolAddress (host symbol decay = host shadow address; on GB300 ATS
// the GPU silently writes host RAM). Device-side references to globals are fine.
#define GRID_ROWS ((N_NODES + 127) / 128)
#define ATTN_GRID ((N_NODES + 7) / 8)

extern "C" void kernel_launch(void* const* d_in, const int* in_sizes, int n_in,
                              void* d_out, int out_size) {
    const float* h     = (const float*)d_in[0];
    const float* W1    = (const float*)d_in[1];
    const float* al1   = (const float*)d_in[2];
    const float* ar1   = (const float*)d_in[3];
    const float* W2    = (const float*)d_in[4];
    const float* al2   = (const float*)d_in[5];
    const float* ar2   = (const float*)d_in[6];
    const float* W3    = (const float*)d_in[7];
    const float* al3   = (const float*)d_in[8];
    const float* ar3   = (const float*)d_in[9];
    const float* resW3 = (const float*)d_in[10];
    const int*   src   = (const int*)d_in[11];
    const int*   dst   = (const int*)d_in[12];
    float* out = (float*)d_out;

    float* g_feat_p; cudaGetSymbolAddress((void**)&g_feat_p, g_feat);
    float* g_x1_p;   cudaGetSymbolAddress((void**)&g_x1_p, g_x1);
    float* g_x2_p;   cudaGetSymbolAddress((void**)&g_x2_p, g_x2);
    float* g_res3_p; cudaGetSymbolAddress((void**)&g_res3_p, g_res3);
    __nv_bfloat16* whi; cudaGetSymbolAddress((void**)&whi, g_wthi);
    __nv_bfloat16* wlo; cudaGetSymbolAddress((void**)&wlo, g_wtlo);

    cudaFuncSetAttribute(mma_gemm_kernel, cudaFuncAttributeMaxDynamicSharedMemorySize,
                         MMA_SMEM_BYTES);

    // converts (also zeroes g_cnt) + CSR build
    convert_x_kernel<<<(N_NODES * 128 + 255) / 256, 256>>>(h);
    convert_w_all_kernel<<<(98304 + 255) / 256, 256>>>(W1, W2, W3, resW3);
    hist_kernel<<<(N_EDGES + 255) / 256, 256>>>(dst);
    scan_kernel<<<1, 1024>>>();
    scatter_kernel<<<(N_EDGES + 255) / 256, 256>>>(src, dst);

    // ---- Layer 1: 128 -> 4x32, residual = h, relu; attn emits bf16 x1
    mma_gemm_kernel<<<dim3(GRID_ROWS, 1), 256, MMA_SMEM_BYTES>>>(
        g_feat_p, 128, whi, wlo, al1, ar1, 32);
    attn_kernel<128, false><<<ATTN_GRID, 256>>>(h, g_x1_p);

    // ---- Layer 2: 128 -> 4x32, residual = x1, relu; attn emits bf16 x2
    mma_gemm_kernel<<<dim3(GRID_ROWS, 1), 256, MMA_SMEM_BYTES>>>(
        g_feat_p, 128, whi + 16384, wlo + 16384, al2, ar2, 32);
    attn_kernel<128, false><<<ATTN_GRID, 256>>>(g_x1_p, g_x2_p);

    // ---- Layer 3 residual projection: res3 = x2 @ resW3
    mma_gemm_kernel<<<dim3(GRID_ROWS, 2), 256, MMA_SMEM_BYTES>>>(
        g_res3_p, 256, whi + 65536, wlo + 65536, nullptr, nullptr, 0);

    // ---- Layer 3: 128 -> 4x64, residual = res3, no act; fused head-mean -> out
    mma_gemm_kernel<<<dim3(GRID_ROWS, 2), 256, MMA_SMEM_BYTES>>>(
        g_feat_p, 256, whi + 32768, wlo + 32768, al3, ar3, 64);
    attn_kernel<256, true><<<ATTN_GRID, 256>>>(g_res3_p, out);
}

// round 13
// speedup vs baseline: 1.8800x; 1.1040x over previous
#include <cuda_runtime.h>
#include <cuda_bf16.h>
#include <math.h>
#include <stdint.h>

#define N_NODES 50000
#define N_EDGES 800000
#define NHEADS 4
#define NEG_SLOPE 0.2f
#define SCAN_BLOCKS 49   // 49 * 1024 = 50176 >= N_NODES

// ---------------- static device scratch (no allocs allowed) ----------------
__device__ __align__(16) float g_feat[N_NODES * 256];   // per-layer linear output [N, H*D]
__device__ __align__(16) float g_x1[N_NODES * 128];     // layer-1 output (fp32, residual use)
__device__ __align__(16) float g_x2[N_NODES * 128];     // layer-2 output
__device__ __align__(16) float g_res3[N_NODES * 256];   // layer-3 residual projection
__device__ __align__(16) float g_el[N_NODES * NHEADS];
__device__ __align__(16) float g_er[N_NODES * NHEADS];
__device__ int   g_cnt[N_NODES];
__device__ int   g_off[N_NODES + 1];
__device__ int   g_cur[N_NODES];
__device__ int   g_csrc[N_EDGES];
__device__ int   g_bsum[SCAN_BLOCKS];
__device__ int   g_bpre[SCAN_BLOCKS];
// bf16 split operands for the tensor-core GEMM
__device__ __align__(16) __nv_bfloat16 g_xhi[N_NODES * 128];
__device__ __align__(16) __nv_bfloat16 g_xlo[N_NODES * 128];
// all weight splits, transposed [m][k]: W1 @0, W2 @16384, W3 @32768, resW3 @65536
// (W3 and resW3 are contiguous: rows 256..511 and 512..767 of the [768][128] view)
__device__ __align__(16) __nv_bfloat16 g_wthi[98304];
__device__ __align__(16) __nv_bfloat16 g_wtlo[98304];

// ================= warp-MMA helpers (baseline sm_80 PTX — no arch-feature
// suffix; tcgen05 is rejected because the harness lowers via compute_103) ====
__device__ __forceinline__ uint32_t cvta_smem(const void* p) {
    uint32_t a;
    asm("{ .reg .u64 t; cvta.to.shared.u64 t, %1; cvt.u32.u64 %0, t; }" : "=r"(a) : "l"(p));
    return a;
}
#define LDSM_X4(R0, R1, R2, R3, ADDR) \
    asm volatile("ldmatrix.sync.aligned.m8n8.x4.shared.b16 {%0,%1,%2,%3}, [%4];" \
                 : "=r"(R0), "=r"(R1), "=r"(R2), "=r"(R3) : "r"(ADDR))
#define MMA_BF16(C, A0, A1, A2, A3, B0, B1) \
    asm volatile("mma.sync.aligned.m16n8k16.row.col.f32.bf16.bf16.f32 " \
                 "{%0,%1,%2,%3},{%4,%5,%6,%7},{%8,%9},{%0,%1,%2,%3};" \
                 : "+f"((C)[0]), "+f"((C)[1]), "+f"((C)[2]), "+f"((C)[3]) \
                 : "r"(A0), "r"(A1), "r"(A2), "r"(A3), "r"(B0), "r"(B1))

// ---------------- CSR build ----------------
__global__ void hist_kernel(const int* __restrict__ dst) {
    int e = blockIdx.x * blockDim.x + threadIdx.x;
    if (e < N_EDGES) atomicAdd(&g_cnt[dst[e]], 1);
}

// parallel scan, stage 1: per-block inclusive scan (49 blocks x 1024)
__global__ void scan_part_kernel() {
    __shared__ int wsum[32];
    int tid = threadIdx.x, lane = tid & 31, wid = tid >> 5;
    int i = blockIdx.x * 1024 + tid;
    int v = (i < N_NODES) ? g_cnt[i] : 0;
    int x = v;
    #pragma unroll
    for (int o = 1; o < 32; o <<= 1) {
        int t = __shfl_up_sync(0xffffffffu, x, o);
        if (lane >= o) x += t;
    }
    if (lane == 31) wsum[wid] = x;
    __syncthreads();
    if (wid == 0) {
        int y = wsum[lane];
        #pragma unroll
        for (int o = 1; o < 32; o <<= 1) {
            int t = __shfl_up_sync(0xffffffffu, y, o);
            if (lane >= o) y += t;
        }
        wsum[lane] = y;
    }
    __syncthreads();
    int incl = x + (wid ? wsum[wid - 1] : 0);
    if (i < N_NODES) g_cur[i] = incl;              // temp: block-local inclusive
    if (tid == 1023) g_bsum[blockIdx.x] = incl;    // block total
}

// stage 2: one warp scans the 49 block sums
__global__ void scan_mid_kernel() {
    int lane = threadIdx.x;
    int carry = 0;
    for (int base = 0; base < SCAN_BLOCKS; base += 32) {
        int v = (base + lane < SCAN_BLOCKS) ? g_bsum[base + lane] : 0;
        int x = v;
        #pragma unroll
        for (int o = 1; o < 32; o <<= 1) {
            int t = __shfl_up_sync(0xffffffffu, x, o);
            if (lane >= o) x += t;
        }
        if (base + lane < SCAN_BLOCKS) g_bpre[base + lane] = carry + x - v;
        carry += __shfl_sync(0xffffffffu, x, 31);
    }
    if (lane == 0) g_off[N_NODES] = carry;
}

// stage 3: compose final exclusive offsets
__global__ void scan_add_kernel() {
    int i = blockIdx.x * blockDim.x + threadIdx.x;
    if (i < N_NODES) {
        int excl = g_bpre[i >> 10] + g_cur[i] - g_cnt[i];
        g_off[i] = excl;
        g_cur[i] = excl;
    }
}

__global__ void scatter_kernel(const int* __restrict__ src, const int* __restrict__ dst) {
    int e = blockIdx.x * blockDim.x + threadIdx.x;
    if (e < N_EDGES) {
        int d = dst[e];
        int p = atomicAdd(&g_cur[d], 1);
        g_csrc[p] = src[e];
    }
}

// ---------------- precision-split converts (also zeroes g_cnt) --------------
__global__ void convert_x_kernel(const float* __restrict__ x) {
    int i = blockIdx.x * blockDim.x + threadIdx.x;
    if (i < N_NODES) g_cnt[i] = 0;
    if (i < N_NODES * 128) {
        float v = x[i];
        __nv_bfloat16 hi = __float2bfloat16(v);
        g_xhi[i] = hi;
        g_xlo[i] = __float2bfloat16(v - __bfloat162float(hi));
    }
}

// all four weight matrices -> transposed bf16 hi/lo in one launch
__global__ void convert_w_all_kernel(const float* __restrict__ W1, const float* __restrict__ W2,
                                     const float* __restrict__ W3, const float* __restrict__ rW3) {
    int i = blockIdx.x * blockDim.x + threadIdx.x;
    if (i >= 98304) return;
    const float* W;
    int M, off;
    if (i < 16384)      { W = W1;  M = 128; off = i; }
    else if (i < 32768) { W = W2;  M = 128; off = i - 16384; }
    else if (i < 65536) { W = W3;  M = 256; off = i - 32768; }
    else                { W = rW3; M = 256; off = i - 65536; }
    int m = off >> 7, k = off & 127;
    float v = W[k * M + m];
    __nv_bfloat16 hi = __float2bfloat16(v);
    g_wthi[i] = hi;
    g_wtlo[i] = __float2bfloat16(v - __bfloat162float(hi));
}

// ---------------- tensor-core GEMM (split-bf16, mma.sync) + el/er epilogue ---
// Layer-3 fusion: when res_out != nullptr, blockIdx.y in 0..3; y<2 computes
// feat (with attention epilogue), y>=2 computes the residual projection into
// res_out (weights for both are contiguous in whi/wlo; same A tile reused).
#define APITCH 136
#define MMA_SMEM_BYTES (4 * 128 * APITCH * 2)

__global__ void __launch_bounds__(256, 1) mma_gemm_kernel(float* __restrict__ out, int M,
        const __nv_bfloat16* __restrict__ whi, const __nv_bfloat16* __restrict__ wlo,
        const float* __restrict__ al, const float* __restrict__ ar, int DA,
        float* __restrict__ res_out) {
    extern __shared__ __nv_bfloat16 sm[];
    __nv_bfloat16* Ahi = sm;
    __nv_bfloat16* Alo = Ahi + 128 * APITCH;
    __nv_bfloat16* Bhi = Alo + 128 * APITCH;
    __nv_bfloat16* Blo = Bhi + 128 * APITCH;
    int tid = threadIdx.x, lane = tid & 31, w = tid >> 5;
    int row0 = blockIdx.x * 128;
    int ycol = blockIdx.y;
    int col0w = ycol * 128;                       // weight row block (into whi/wlo)
    bool resPath = (res_out != nullptr) && (ycol >= 2);
    int col0 = resPath ? (ycol - 2) * 128 : ycol * 128;
    float* dst = resPath ? res_out : out;
    int DAe = resPath ? 0 : DA;

    for (int i = tid; i < 2048; i += 256) {
        int r = i >> 4, c = (i & 15) * 8;
        int gr = row0 + r;
        uint4 vh = make_uint4(0, 0, 0, 0), vl = vh;
        if (gr < N_NODES) {
            vh = *(const uint4*)(g_xhi + gr * 128 + c);
            vl = *(const uint4*)(g_xlo + gr * 128 + c);
        }
        *(uint4*)(Ahi + r * APITCH + c) = vh;
        *(uint4*)(Alo + r * APITCH + c) = vl;
        int gn = col0w + r;
        *(uint4*)(Bhi + r * APITCH + c) = *(const uint4*)(whi + gn * 128 + c);
        *(uint4*)(Blo + r * APITCH + c) = *(const uint4*)(wlo + gn * 128 + c);
    }
    __syncthreads();

    float c[16][4];
    #pragma unroll
    for (int i = 0; i < 16; i++)
        #pragma unroll
        for (int j = 0; j < 4; j++) c[i][j] = 0.f;

    int l7 = lane & 7, mi = lane >> 3;
    int arow = w * 16 + (mi & 1) * 8 + l7;
    int akof = (mi >> 1) * 8;
    uint32_t a_hi_ad = cvta_smem(Ahi) + (uint32_t)(arow * APITCH + akof) * 2;
    uint32_t a_lo_ad = cvta_smem(Alo) + (uint32_t)(arow * APITCH + akof) * 2;
    int bn = (mi >> 1) * 8 + l7;
    int bkof = (mi & 1) * 8;
    uint32_t b_hi_ad = cvta_smem(Bhi) + (uint32_t)(bn * APITCH + bkof) * 2;
    uint32_t b_lo_ad = cvta_smem(Blo) + (uint32_t)(bn * APITCH + bkof) * 2;

    for (int ks = 0; ks < 8; ks++) {
        uint32_t ah0, ah1, ah2, ah3, al0r, al1r, al2r, al3r;
        LDSM_X4(ah0, ah1, ah2, ah3, a_hi_ad + ks * 32);
        LDSM_X4(al0r, al1r, al2r, al3r, a_lo_ad + ks * 32);
        #pragma unroll
        for (int np = 0; np < 8; np++) {
            uint32_t bh0, bh1, bh2, bh3, bl0, bl1, bl2, bl3;
            uint32_t bo = (uint32_t)(np * 16 * APITCH) * 2 + ks * 32;
            LDSM_X4(bh0, bh1, bh2, bh3, b_hi_ad + bo);
            LDSM_X4(bl0, bl1, bl2, bl3, b_lo_ad + bo);
            int nt = 2 * np;
            MMA_BF16(c[nt],     ah0, ah1, ah2, ah3, bh0, bh1);
            MMA_BF16(c[nt],     ah0, ah1, ah2, ah3, bl0, bl1);
            MMA_BF16(c[nt],     al0r, al1r, al2r, al3r, bh0, bh1);
            MMA_BF16(c[nt + 1], ah0, ah1, ah2, ah3, bh2, bh3);
            MMA_BF16(c[nt + 1], ah0, ah1, ah2, ah3, bl2, bl3);
            MMA_BF16(c[nt + 1], al0r, al1r, al2r, al3r, bh2, bh3);
        }
    }

    int t = lane & 3, g2 = lane >> 2;
    int rlo = row0 + w * 16 + g2, rhi = rlo + 8;
    float elL[4] = {0, 0, 0, 0}, erL[4] = {0, 0, 0, 0};
    float elH[4] = {0, 0, 0, 0}, erH[4] = {0, 0, 0, 0};
    #pragma unroll
    for (int nt = 0; nt < 16; nt++) {
        int gc = col0 + nt * 8 + 2 * t;
        if (rlo < N_NODES)
            *(float2*)(dst + rlo * M + gc) = make_float2(c[nt][0], c[nt][1]);
        if (rhi < N_NODES)
            *(float2*)(dst + rhi * M + gc) = make_float2(c[nt][2], c[nt][3]);
        if (DAe) {
            int b = (DAe == 32) ? (nt >> 2) : (nt >> 3);
            float a0v = al[gc], a1v = al[gc + 1];
            float r0v = ar[gc], r1v = ar[gc + 1];
            elL[b] += c[nt][0] * a0v + c[nt][1] * a1v;
            erL[b] += c[nt][0] * r0v + c[nt][1] * r1v;
            elH[b] += c[nt][2] * a0v + c[nt][3] * a1v;
            erH[b] += c[nt][2] * r0v + c[nt][3] * r1v;
        }
    }
    if (DAe) {
        int nb = 128 / DAe;
        #pragma unroll
        for (int b = 0; b < 4; b++) {
            if (b >= nb) break;
            #pragma unroll
            for (int o = 1; o < 4; o <<= 1) {
                elL[b] += __shfl_xor_sync(0xffffffffu, elL[b], o);
                erL[b] += __shfl_xor_sync(0xffffffffu, erL[b], o);
                elH[b] += __shfl_xor_sync(0xffffffffu, elH[b], o);
                erH[b] += __shfl_xor_sync(0xffffffffu, erH[b], o);
            }
            if (t == 0) {
                int h = col0 / DAe + b;
                if (rlo < N_NODES) {
                    g_el[rlo * NHEADS + h] = elL[b];
                    g_er[rlo * NHEADS + h] = erL[b];
                }
                if (rhi < N_NODES) {
                    g_el[rhi * NHEADS + h] = elH[b];
                    g_er[rhi * NHEADS + h] = erH[b];
                }
            }
        }
    }
}

// ---------------- fused edge softmax + aggregation: warp per NODE ----------
template<int MM, bool FINAL>
__global__ void __launch_bounds__(256) attn_kernel(const float* __restrict__ res,
                                                   float* __restrict__ out) {
    __shared__ int   sh_s[8][32];
    __shared__ float sh_w[8][128];
    int wslot = threadIdx.x >> 5, lane = threadIdx.x & 31;
    int n = blockIdx.x * 8 + wslot;
    if (n >= N_NODES) return;   // uniform per warp
    int beg = g_off[n], end = g_off[n + 1];
    float4 er4 = *(const float4*)(g_er + n * 4);
    float4 den = make_float4(0.f, 0.f, 0.f, 0.f);
    float4 acc0 = make_float4(0.f, 0.f, 0.f, 0.f);
    float4 acc1 = make_float4(0.f, 0.f, 0.f, 0.f);
    int myh = (MM == 128) ? (lane >> 3) : (lane >> 4);

    for (int j0 = beg; j0 < end; j0 += 32) {
        int j = j0 + lane;
        float4 w4 = make_float4(0.f, 0.f, 0.f, 0.f);
        int s = 0;
        if (j < end) {
            s = g_csrc[j];
            float4 el4 = *(const float4*)(g_el + s * 4);
            float e0 = el4.x + er4.x; e0 = e0 > 0.f ? e0 : NEG_SLOPE * e0;
            float e1 = el4.y + er4.y; e1 = e1 > 0.f ? e1 : NEG_SLOPE * e1;
            float e2 = el4.z + er4.z; e2 = e2 > 0.f ? e2 : NEG_SLOPE * e2;
            float e3 = el4.w + er4.w; e3 = e3 > 0.f ? e3 : NEG_SLOPE * e3;
            w4.x = __expf(fminf(e0, 60.f));
            w4.y = __expf(fminf(e1, 60.f));
            w4.z = __expf(fminf(e2, 60.f));
            w4.w = __expf(fminf(e3, 60.f));
            den.x += w4.x; den.y += w4.y; den.z += w4.z; den.w += w4.w;
        }
        sh_s[wslot][lane] = s;
        *(float4*)&sh_w[wslot][lane * 4] = w4;
        __syncwarp();
        int cnt = min(32, end - j0);
        #pragma unroll 4
        for (int t = 0; t < cnt; t++) {
            int st = sh_s[wslot][t];
            const float* fp = g_feat + st * MM;
            if (MM == 128) {
                float wt = sh_w[wslot][t * 4 + myh];
                float4 f = *(const float4*)(fp + lane * 4);
                acc0.x = fmaf(wt, f.x, acc0.x);
                acc0.y = fmaf(wt, f.y, acc0.y);
                acc0.z = fmaf(wt, f.z, acc0.z);
                acc0.w = fmaf(wt, f.w, acc0.w);
            } else {
                float wt0 = sh_w[wslot][t * 4 + myh];
                float wt1 = sh_w[wslot][t * 4 + 2 + myh];
                float4 f0 = *(const float4*)(fp + lane * 4);
                float4 f1 = *(const float4*)(fp + 128 + lane * 4);
                acc0.x = fmaf(wt0, f0.x, acc0.x);
                acc0.y = fmaf(wt0, f0.y, acc0.y);
                acc0.z = fmaf(wt0, f0.z, acc0.z);
                acc0.w = fmaf(wt0, f0.w, acc0.w);
                acc1.x = fmaf(wt1, f1.x, acc1.x);
                acc1.y = fmaf(wt1, f1.y, acc1.y);
                acc1.z = fmaf(wt1, f1.z, acc1.z);
                acc1.w = fmaf(wt1, f1.w, acc1.w);
            }
        }
        __syncwarp();
    }

    #pragma unroll
    for (int o = 16; o; o >>= 1) {
        den.x += __shfl_xor_sync(0xffffffffu, den.x, o);
        den.y += __shfl_xor_sync(0xffffffffu, den.y, o);
        den.z += __shfl_xor_sync(0xffffffffu, den.z, o);
        den.w += __shfl_xor_sync(0xffffffffu, den.w, o);
    }
    bool ne = end > beg;

    if (MM == 128) {
        float a = (lane & 8) ? den.y : den.x;
        float b = (lane & 8) ? den.w : den.z;
        float dv = (lane & 16) ? b : a;
        float inv = ne ? 1.f / dv : 0.f;
        float4 r = *(const float4*)(res + n * 128 + lane * 4);
        float4 v;
        v.x = fmaxf(fmaf(acc0.x, inv, r.x), 0.f);
        v.y = fmaxf(fmaf(acc0.y, inv, r.y), 0.f);
        v.z = fmaxf(fmaf(acc0.z, inv, r.z), 0.f);
        v.w = fmaxf(fmaf(acc0.w, inv, r.w), 0.f);
        *(float4*)(out + n * 128 + lane * 4) = v;
        __nv_bfloat16 hx = __float2bfloat16(v.x), hy = __float2bfloat16(v.y);
        __nv_bfloat16 hz = __float2bfloat16(v.z), hw = __float2bfloat16(v.w);
        __nv_bfloat162 hA; hA.x = hx; hA.y = hy;
        __nv_bfloat162 hB; hB.x = hz; hB.y = hw;
        *(__nv_bfloat162*)(g_xhi + n * 128 + lane * 4) = hA;
        *(__nv_bfloat162*)(g_xhi + n * 128 + lane * 4 + 2) = hB;
        __nv_bfloat162 lA, lB;
        lA.x = __float2bfloat16(v.x - __bfloat162float(hx));
        lA.y = __float2bfloat16(v.y - __bfloat162float(hy));
        lB.x = __float2bfloat16(v.z - __bfloat162float(hz));
        lB.y = __float2bfloat16(v.w - __bfloat162float(hw));
        *(__nv_bfloat162*)(g_xlo + n * 128 + lane * 4) = lA;
        *(__nv_bfloat162*)(g_xlo + n * 128 + lane * 4 + 2) = lB;
    } else {
        float dv0 = (lane & 16) ? den.y : den.x;
        float dv1 = (lane & 16) ? den.w : den.z;
        float inv0 = ne ? 1.f / dv0 : 0.f;
        float inv1 = ne ? 1.f / dv1 : 0.f;
        float4 r0 = *(const float4*)(res + n * 256 + lane * 4);
        float4 r1 = *(const float4*)(res + n * 256 + 128 + lane * 4);
        float4 v0, v1;
        v0.x = fmaf(acc0.x, inv0, r0.x); v0.y = fmaf(acc0.y, inv0, r0.y);
        v0.z = fmaf(acc0.z, inv0, r0.z); v0.w = fmaf(acc0.w, inv0, r0.w);
        v1.x = fmaf(acc1.x, inv1, r1.x); v1.y = fmaf(acc1.y, inv1, r1.y);
        v1.z = fmaf(acc1.z, inv1, r1.z); v1.w = fmaf(acc1.w, inv1, r1.w);
        v0.x += __shfl_xor_sync(0xffffffffu, v0.x, 16);
        v0.y += __shfl_xor_sync(0xffffffffu, v0.y, 16);
        v0.z += __shfl_xor_sync(0xffffffffu, v0.z, 16);
        v0.w += __shfl_xor_sync(0xffffffffu, v0.w, 16);
        v1.x += __shfl_xor_sync(0xffffffffu, v1.x, 16);
        v1.y += __shfl_xor_sync(0xffffffffu, v1.y, 16);
        v1.z += __shfl_xor_sync(0xffffffffu, v1.z, 16);
        v1.w += __shfl_xor_sync(0xffffffffu, v1.w, 16);
        if (lane < 16) {
            float4 tot;
            tot.x = 0.25f * (v0.x + v1.x);
            tot.y = 0.25f * (v0.y + v1.y);
            tot.z = 0.25f * (v0.z + v1.z);
            tot.w = 0.25f * (v0.w + v1.w);
            *(float4*)(out + n * 64 + lane * 4) = tot;
        }
    }
}

// ---------------- launch ----------------
// NOTE: device buffers passed as kernel args from host MUST come from
// cudaGetSymbolAddress (host symbol decay = host shadow address; on GB300 ATS
// the GPU silently writes host RAM). Device-side references to globals are fine.
#define GRID_ROWS ((N_NODES + 127) / 128)
#define ATTN_GRID ((N_NODES + 7) / 8)

extern "C" void kernel_launch(void* const* d_in, const int* in_sizes, int n_in,
                              void* d_out, int out_size) {
    const float* h     = (const float*)d_in[0];
    const float* W1    = (const float*)d_in[1];
    const float* al1   = (const float*)d_in[2];
    const float* ar1   = (const float*)d_in[3];
    const float* W2    = (const float*)d_in[4];
    const float* al2   = (const float*)d_in[5];
    const float* ar2   = (const float*)d_in[6];
    const float* W3    = (const float*)d_in[7];
    const float* al3   = (const float*)d_in[8];
    const float* ar3   = (const float*)d_in[9];
    const float* resW3 = (const float*)d_in[10];
    const int*   src   = (const int*)d_in[11];
    const int*   dst   = (const int*)d_in[12];
    float* out = (float*)d_out;

    float* g_feat_p; cudaGetSymbolAddress((void**)&g_feat_p, g_feat);
    float* g_x1_p;   cudaGetSymbolAddress((void**)&g_x1_p, g_x1);
    float* g_x2_p;   cudaGetSymbolAddress((void**)&g_x2_p, g_x2);
    float* g_res3_p; cudaGetSymbolAddress((void**)&g_res3_p, g_res3);
    __nv_bfloat16* whi; cudaGetSymbolAddress((void**)&whi, g_wthi);
    __nv_bfloat16* wlo; cudaGetSymbolAddress((void**)&wlo, g_wtlo);

    cudaFuncSetAttribute(mma_gemm_kernel, cudaFuncAttributeMaxDynamicSharedMemorySize,
                         MMA_SMEM_BYTES);

    // converts (also zeroes g_cnt) + CSR build (3-stage parallel scan)
    convert_x_kernel<<<(N_NODES * 128 + 255) / 256, 256>>>(h);
    convert_w_all_kernel<<<(98304 + 255) / 256, 256>>>(W1, W2, W3, resW3);
    hist_kernel<<<(N_EDGES + 255) / 256, 256>>>(dst);
    scan_part_kernel<<<SCAN_BLOCKS, 1024>>>();
    scan_mid_kernel<<<1, 32>>>();
    scan_add_kernel<<<(N_NODES + 255) / 256, 256>>>();
    scatter_kernel<<<(N_EDGES + 255) / 256, 256>>>(src, dst);

    // ---- Layer 1: 128 -> 4x32, residual = h, relu; attn emits bf16 x1
    mma_gemm_kernel<<<dim3(GRID_ROWS, 1), 256, MMA_SMEM_BYTES>>>(
        g_feat_p, 128, whi, wlo, al1, ar1, 32, nullptr);
    attn_kernel<128, false><<<ATTN_GRID, 256>>>(h, g_x1_p);

    // ---- Layer 2: 128 -> 4x32, residual = x1, relu; attn emits bf16 x2
    mma_gemm_kernel<<<dim3(GRID_ROWS, 1), 256, MMA_SMEM_BYTES>>>(
        g_feat_p, 128, whi + 16384, wlo + 16384, al2, ar2, 32, nullptr);
    attn_kernel<128, false><<<ATTN_GRID, 256>>>(g_x1_p, g_x2_p);

    // ---- Layer 3 fused: feat = x2@W3 (y=0,1 with el/er epilogue) AND
    //      res3 = x2@resW3 (y=2,3), same A tile, contiguous weights
    mma_gemm_kernel<<<dim3(GRID_ROWS, 4), 256, MMA_SMEM_BYTES>>>(
        g_feat_p, 256, whi + 32768, wlo + 32768, al3, ar3, 64, g_res3_p);
    attn_kernel<256, true><<<ATTN_GRID, 256>>>(g_res3_p, out);
}